// round 3
// baseline (speedup 1.0000x reference)
#include <cuda_runtime.h>
#include <math_constants.h>

#define B_ROWS 32768
#define C_COLS 1000
#define C_VEC4 250            // 1000 / 4

// Device-global scratch (no allocations, no host-side symbol lookups).
__device__ double g_rowloss[B_ROWS];

// Insert v into descending sorted (t0 >= t1 >= t2 >= t3)
__device__ __forceinline__ void insert4(float v, float& t0, float& t1, float& t2, float& t3) {
    if (v > t3) {
        if (v > t1) {
            if (v > t0) { t3 = t2; t2 = t1; t1 = t0; t0 = v; }
            else        { t3 = t2; t2 = t1; t1 = v; }
        } else {
            if (v > t2) { t3 = t2; t2 = v; }
            else        { t3 = v; }
        }
    }
}

// Merge two descending sorted 4-lists -> top-4 of the union, descending, in a.
// [a0..a3, b3..b0] is bitonic; one CE stage keeps the 4 largest (still bitonic),
// then a 4-wide bitonic sorter orders them. Branchless fmax/fmin, registers only.
__device__ __forceinline__ void merge4(float& a0, float& a1, float& a2, float& a3,
                                       float b0, float b1, float b2, float b3) {
    float e0 = fmaxf(a0, b3);
    float e1 = fmaxf(a1, b2);
    float e2 = fmaxf(a2, b1);
    float e3 = fmaxf(a3, b0);
    float g0 = fmaxf(e0, e2), g2 = fminf(e0, e2);
    float g1 = fmaxf(e1, e3), g3 = fminf(e1, e3);
    a0 = fmaxf(g0, g1); a1 = fminf(g0, g1);
    a2 = fmaxf(g2, g3); a3 = fminf(g2, g3);
}

__global__ __launch_bounds__(256, 8)
void rowloss_kernel(const float* __restrict__ logits,
                    const int* __restrict__ labels32) {
    const int warp = (blockIdx.x * blockDim.x + threadIdx.x) >> 5;
    const int lane = threadIdx.x & 31;
    if (warp >= B_ROWS) return;

    // --- Label dtype probe (uniform across all warps; deterministic) ---
    // int64 little-endian layout with labels < 1000 => every odd 32-bit word is 0.
    // int32 layout => odd words are labels, all-zero with prob 1e-12.
    const bool is64 = ((labels32[1] | labels32[3] | labels32[5] | labels32[7]) == 0);
    const int label = is64 ? labels32[2 * warp] : labels32[warp];

    const float4* __restrict__ row =
        reinterpret_cast<const float4*>(logits + (size_t)warp * C_COLS);

    float t0 = -CUDART_INF_F, t1 = -CUDART_INF_F, t2 = -CUDART_INF_F, t3 = -CUDART_INF_F;
    float lab = -CUDART_INF_F;

    #pragma unroll
    for (int it = 0; it < 8; ++it) {
        const int i4 = it * 32 + lane;
        if (i4 < C_VEC4) {
            const float4 v = row[i4];
            const int base = i4 * 4;
            if (base + 0 == label) lab = v.x; else insert4(v.x, t0, t1, t2, t3);
            if (base + 1 == label) lab = v.y; else insert4(v.y, t0, t1, t2, t3);
            if (base + 2 == label) lab = v.z; else insert4(v.z, t0, t1, t2, t3);
            if (base + 3 == label) lab = v.w; else insert4(v.w, t0, t1, t2, t3);
        }
    }

    // Broadcast the label logit (exactly one lane holds it; others have -inf)
    #pragma unroll
    for (int off = 16; off; off >>= 1)
        lab = fmaxf(lab, __shfl_xor_sync(0xffffffffu, lab, off));

    // Butterfly-merge per-lane sorted top-4 lists into the row's global top-4
    #pragma unroll
    for (int off = 16; off; off >>= 1) {
        float b0 = __shfl_xor_sync(0xffffffffu, t0, off);
        float b1 = __shfl_xor_sync(0xffffffffu, t1, off);
        float b2 = __shfl_xor_sync(0xffffffffu, t2, off);
        float b3 = __shfl_xor_sync(0xffffffffu, t3, off);
        merge4(t0, t1, t2, t3, b0, b1, b2, b3);
    }

    if (lane == 0) {
        // loss = logsumexp([lab, t0..t3]) - lab, in double for headroom.
        const double dl = (double)lab;
        const double m  = fmax(dl, (double)t0);
        const double s  = exp(dl - m) + exp((double)t0 - m) + exp((double)t1 - m)
                        + exp((double)t2 - m) + exp((double)t3 - m);
        g_rowloss[warp] = log(s) + m - dl;
    }
}

__global__ void reduce_kernel(float* __restrict__ out) {
    __shared__ double sh[1024];
    const int tid = threadIdx.x;
    double s = 0.0;
    #pragma unroll
    for (int i = tid; i < B_ROWS; i += 1024) s += g_rowloss[i];
    sh[tid] = s;
    __syncthreads();
    #pragma unroll
    for (int off = 512; off; off >>= 1) {
        if (tid < off) sh[tid] += sh[tid + off];
        __syncthreads();
    }
    if (tid == 0) out[0] = (float)(sh[0] * (1.0 / (double)B_ROWS));
}

extern "C" void kernel_launch(void* const* d_in, const int* in_sizes, int n_in,
                              void* d_out, int out_size) {
    const float* logits   = (const float*)d_in[0];
    const int*   labels32 = (const int*)d_in[1];   // dtype probed in-kernel
    float* out = (float*)d_out;

    // 8 warps (rows) per 256-thread block; no host CUDA API calls here.
    rowloss_kernel<<<B_ROWS / 8, 256>>>(logits, labels32);
    reduce_kernel<<<1, 1024>>>(out);
}

// round 4
// speedup vs baseline: 7.5000x; 7.5000x over previous
#include <cuda_runtime.h>
#include <math_constants.h>

#define B_ROWS 32768
#define C_COLS 1000
#define C_VEC4 250              // 1000 / 4
#define NBLK   (B_ROWS / 8)     // 8 rows (warps) per block

__device__ float g_partial[NBLK];

// Branchless: keep top-4 of {t0..t3, v}, descending. 7 fmax/fmin, no divergence.
__device__ __forceinline__ void insert4(float v, float& t0, float& t1, float& t2, float& t3) {
    t3 = fmaxf(t3, v);                               // drop min of the 5
    float a;
    a = fmaxf(t2, t3); t3 = fminf(t2, t3); t2 = a;   // bubble t3 into place
    a = fmaxf(t1, t2); t2 = fminf(t1, t2); t1 = a;
    a = fmaxf(t0, t1); t1 = fminf(t0, t1); t0 = a;
}

// Merge two descending sorted 4-lists -> top-4 of the union, descending, in a.
__device__ __forceinline__ void merge4(float& a0, float& a1, float& a2, float& a3,
                                       float b0, float b1, float b2, float b3) {
    float e0 = fmaxf(a0, b3);
    float e1 = fmaxf(a1, b2);
    float e2 = fmaxf(a2, b1);
    float e3 = fmaxf(a3, b0);
    float g0 = fmaxf(e0, e2), g2 = fminf(e0, e2);
    float g1 = fmaxf(e1, e3), g3 = fminf(e1, e3);
    a0 = fmaxf(g0, g1); a1 = fminf(g0, g1);
    a2 = fmaxf(g2, g3); a3 = fminf(g2, g3);
}

__global__ __launch_bounds__(256)
void rowloss_kernel(const float* __restrict__ logits,
                    const int* __restrict__ labels32) {
    const int warp = (blockIdx.x * blockDim.x + threadIdx.x) >> 5;
    const int wib  = (threadIdx.x >> 5);       // warp in block (row slot)
    const int lane = threadIdx.x & 31;

    // Label dtype probe: int64-LE with labels<1000 => all odd 32-bit words zero.
    const bool is64 = ((labels32[1] | labels32[3] | labels32[5] | labels32[7]) == 0);
    const int label = is64 ? labels32[2 * warp] : labels32[warp];

    const float4* __restrict__ row =
        reinterpret_cast<const float4*>(logits + (size_t)warp * C_COLS);

    // ---- Batch all loads up front: MLP=8, DRAM latency fully overlapped ----
    float4 v[8];
    #pragma unroll
    for (int it = 0; it < 8; ++it) {
        int i4 = it * 32 + lane;
        v[it] = row[i4 < C_VEC4 ? i4 : (C_VEC4 - 1)];   // clamp (in-bounds), mask below
    }

    float t0 = -CUDART_INF_F, t1 = -CUDART_INF_F, t2 = -CUDART_INF_F, t3 = -CUDART_INF_F;
    float lab = -CUDART_INF_F;

    #pragma unroll
    for (int it = 0; it < 8; ++it) {
        const int i4 = it * 32 + lane;
        const int base = i4 * 4;
        if (i4 >= C_VEC4) {                    // tail lanes: neutralize clamped dup
            v[it].x = v[it].y = v[it].z = v[it].w = -CUDART_INF_F;
        }
        const unsigned d = (unsigned)(label - base);
        if (d < 4u) {                          // rare: this quad holds the label
            if      (d == 0u) { lab = v[it].x; v[it].x = -CUDART_INF_F; }
            else if (d == 1u) { lab = v[it].y; v[it].y = -CUDART_INF_F; }
            else if (d == 2u) { lab = v[it].z; v[it].z = -CUDART_INF_F; }
            else              { lab = v[it].w; v[it].w = -CUDART_INF_F; }
        }
        insert4(v[it].x, t0, t1, t2, t3);
        insert4(v[it].y, t0, t1, t2, t3);
        insert4(v[it].z, t0, t1, t2, t3);
        insert4(v[it].w, t0, t1, t2, t3);
    }

    // Broadcast label logit (exactly one lane holds it)
    #pragma unroll
    for (int off = 16; off; off >>= 1)
        lab = fmaxf(lab, __shfl_xor_sync(0xffffffffu, lab, off));

    // Butterfly-merge per-lane sorted top-4 lists into the row's global top-4
    #pragma unroll
    for (int off = 16; off; off >>= 1) {
        float b0 = __shfl_xor_sync(0xffffffffu, t0, off);
        float b1 = __shfl_xor_sync(0xffffffffu, t1, off);
        float b2 = __shfl_xor_sync(0xffffffffu, t2, off);
        float b3 = __shfl_xor_sync(0xffffffffu, t3, off);
        merge4(t0, t1, t2, t3, b0, b1, b2, b3);
    }

    // Per-block partial sum of the 8 row losses (deterministic order)
    __shared__ float sh_loss[8];
    if (lane == 0) {
        const float m = fmaxf(lab, t0);
        const float s = expf(lab - m) + expf(t0 - m) + expf(t1 - m)
                      + expf(t2 - m) + expf(t3 - m);
        sh_loss[wib] = logf(s) + m - lab;
    }
    __syncthreads();
    if (threadIdx.x == 0) {
        float acc = 0.0f;
        #pragma unroll
        for (int i = 0; i < 8; ++i) acc += sh_loss[i];
        g_partial[blockIdx.x] = acc;
    }
}

__global__ void reduce_kernel(float* __restrict__ out) {
    __shared__ double sh[1024];
    const int tid = threadIdx.x;
    double s = 0.0;
    #pragma unroll
    for (int i = tid; i < NBLK; i += 1024) s += (double)g_partial[i];
    sh[tid] = s;
    __syncthreads();
    #pragma unroll
    for (int off = 512; off; off >>= 1) {
        if (tid < off) sh[tid] += sh[tid + off];
        __syncthreads();
    }
    if (tid == 0) out[0] = (float)(sh[0] * (1.0 / (double)B_ROWS));
}

extern "C" void kernel_launch(void* const* d_in, const int* in_sizes, int n_in,
                              void* d_out, int out_size) {
    const float* logits   = (const float*)d_in[0];
    const int*   labels32 = (const int*)d_in[1];   // dtype probed in-kernel
    float* out = (float*)d_out;

    rowloss_kernel<<<NBLK, 256>>>(logits, labels32);
    reduce_kernel<<<1, 1024>>>(out);
}

// round 5
// speedup vs baseline: 8.5981x; 1.1464x over previous
#include <cuda_runtime.h>
#include <math_constants.h>

#define B_ROWS 32768
#define C_COLS 1000
#define C_VEC4 250              // 1000 / 4
#define NBLK   (B_ROWS / 8)     // 8 rows (warps) per block
#define FIXSCALE 4294967296.0   // 2^32

// Deterministic accumulator: integer atomics are exactly associative, so the
// sum is bit-identical on every graph replay regardless of block order.
__device__ unsigned long long g_acc   = 0ULL;
__device__ unsigned int       g_count = 0u;

// Merge two descending sorted 4-lists -> top-4 of the union, descending, in a.
__device__ __forceinline__ void merge4(float& a0, float& a1, float& a2, float& a3,
                                       float b0, float b1, float b2, float b3) {
    float e0 = fmaxf(a0, b3);
    float e1 = fmaxf(a1, b2);
    float e2 = fmaxf(a2, b1);
    float e3 = fmaxf(a3, b0);
    float g0 = fmaxf(e0, e2), g2 = fminf(e0, e2);
    float g1 = fmaxf(e1, e3), g3 = fminf(e1, e3);
    a0 = fmaxf(g0, g1); a1 = fminf(g0, g1);
    a2 = fmaxf(g2, g3); a3 = fminf(g2, g3);
}

// Sort 4 arbitrary values descending: 5 comparators, 10 fmax/fmin, depth 3.
__device__ __forceinline__ void sort4(float& x, float& y, float& z, float& w) {
    float s0 = fmaxf(x, y), s1 = fminf(x, y);
    float s2 = fmaxf(z, w), s3 = fminf(z, w);
    float m0 = fmaxf(s0, s2), m2 = fminf(s0, s2);
    float m1 = fmaxf(s1, s3), m3 = fminf(s1, s3);
    x = m0;
    y = fmaxf(m1, m2);
    z = fminf(m1, m2);
    w = m3;
}

__global__ __launch_bounds__(256)
void rowloss_kernel(const float* __restrict__ logits,
                    const int* __restrict__ labels32,
                    float* __restrict__ out) {
    const int warp = (blockIdx.x * blockDim.x + threadIdx.x) >> 5;
    const int wib  = (threadIdx.x >> 5);       // warp in block (row slot)
    const int lane = threadIdx.x & 31;

    // Label dtype probe: int64-LE with labels<1000 => all odd 32-bit words zero.
    const bool is64 = ((labels32[1] | labels32[3] | labels32[5] | labels32[7]) == 0);
    const int label = is64 ? labels32[2 * warp] : labels32[warp];

    const float4* __restrict__ row =
        reinterpret_cast<const float4*>(logits + (size_t)warp * C_COLS);

    // ---- Batch all loads up front: MLP=8, DRAM latency fully overlapped ----
    float4 v[8];
    #pragma unroll
    for (int it = 0; it < 8; ++it) {
        int i4 = it * 32 + lane;
        v[it] = __ldcs(&row[i4 < C_VEC4 ? i4 : (C_VEC4 - 1)]);  // streaming, read-once
    }

    float t0 = -CUDART_INF_F, t1 = -CUDART_INF_F, t2 = -CUDART_INF_F, t3 = -CUDART_INF_F;
    float lab = -CUDART_INF_F;

    #pragma unroll
    for (int it = 0; it < 8; ++it) {
        const int i4 = it * 32 + lane;
        const int base = i4 * 4;
        if (i4 >= C_VEC4) {                    // tail lanes: neutralize clamped dup
            v[it].x = v[it].y = v[it].z = v[it].w = -CUDART_INF_F;
        }
        const unsigned d = (unsigned)(label - base);
        if (d < 4u) {                          // rare: this quad holds the label
            if      (d == 0u) { lab = v[it].x; v[it].x = -CUDART_INF_F; }
            else if (d == 1u) { lab = v[it].y; v[it].y = -CUDART_INF_F; }
            else if (d == 2u) { lab = v[it].z; v[it].z = -CUDART_INF_F; }
            else              { lab = v[it].w; v[it].w = -CUDART_INF_F; }
        }
        // Sort the quad, then one 4x4 merge: 22 ops / 4 elems, shallow chains.
        sort4(v[it].x, v[it].y, v[it].z, v[it].w);
        merge4(t0, t1, t2, t3, v[it].x, v[it].y, v[it].z, v[it].w);
    }

    // Broadcast label logit (exactly one lane holds it)
    #pragma unroll
    for (int off = 16; off; off >>= 1)
        lab = fmaxf(lab, __shfl_xor_sync(0xffffffffu, lab, off));

    // Butterfly-merge per-lane sorted top-4 lists into the row's global top-4
    #pragma unroll
    for (int off = 16; off; off >>= 1) {
        float b0 = __shfl_xor_sync(0xffffffffu, t0, off);
        float b1 = __shfl_xor_sync(0xffffffffu, t1, off);
        float b2 = __shfl_xor_sync(0xffffffffu, t2, off);
        float b3 = __shfl_xor_sync(0xffffffffu, t3, off);
        merge4(t0, t1, t2, t3, b0, b1, b2, b3);
    }

    // Per-block partial: 8 row losses, summed in deterministic order
    __shared__ float sh_loss[8];
    if (lane == 0) {
        const float m = fmaxf(lab, t0);
        const float s = expf(lab - m) + expf(t0 - m) + expf(t1 - m)
                      + expf(t2 - m) + expf(t3 - m);
        sh_loss[wib] = logf(s) + m - lab;      // loss >= 0 always
    }
    __syncthreads();

    if (threadIdx.x == 0) {
        double acc = 0.0;
        #pragma unroll
        for (int i = 0; i < 8; ++i) acc += (double)sh_loss[i];
        // Fixed-point (2^32) deterministic accumulation
        atomicAdd(&g_acc, (unsigned long long)(acc * FIXSCALE));
        __threadfence();
        const unsigned ticket = atomicAdd(&g_count, 1u);
        if (ticket == (unsigned)(NBLK - 1)) {  // last block: finalize + reset
            const unsigned long long total = atomicAdd(&g_acc, 0ULL);
            out[0] = (float)((double)total * (1.0 / FIXSCALE) * (1.0 / (double)B_ROWS));
            g_acc   = 0ULL;                    // replay-safe reset
            __threadfence();
            g_count = 0u;
        }
    }
}

extern "C" void kernel_launch(void* const* d_in, const int* in_sizes, int n_in,
                              void* d_out, int out_size) {
    const float* logits   = (const float*)d_in[0];
    const int*   labels32 = (const int*)d_in[1];   // dtype probed in-kernel
    float* out = (float*)d_out;

    rowloss_kernel<<<NBLK, 256>>>(logits, labels32, out);
}

// round 6
// speedup vs baseline: 9.0690x; 1.0548x over previous
#include <cuda_runtime.h>
#include <math_constants.h>

#define B_ROWS 32768
#define C_COLS 1000
#define C_VEC4 250               // 1000 / 4
#define WPB    4                 // warps per block (128 threads)
#define RPW    2                 // rows per warp
#define NBLK   (B_ROWS / (WPB * RPW))   // 4096 blocks
#define FIXSCALE 4294967296.0    // 2^32

// Deterministic accumulator: integer atomics are exactly associative ->
// bit-identical result on every graph replay regardless of block order.
__device__ unsigned long long g_acc   = 0ULL;
__device__ unsigned int       g_count = 0u;

// Merge two descending sorted 4-lists -> top-4 of the union, descending, in a.
__device__ __forceinline__ void merge4(float& a0, float& a1, float& a2, float& a3,
                                       float b0, float b1, float b2, float b3) {
    float e0 = fmaxf(a0, b3);
    float e1 = fmaxf(a1, b2);
    float e2 = fmaxf(a2, b1);
    float e3 = fmaxf(a3, b0);
    float g0 = fmaxf(e0, e2), g2 = fminf(e0, e2);
    float g1 = fmaxf(e1, e3), g3 = fminf(e1, e3);
    a0 = fmaxf(g0, g1); a1 = fminf(g0, g1);
    a2 = fmaxf(g2, g3); a3 = fminf(g2, g3);
}

// Sort 4 arbitrary values descending: 5 comparators, depth 3.
__device__ __forceinline__ void sort4(float& x, float& y, float& z, float& w) {
    float s0 = fmaxf(x, y), s1 = fminf(x, y);
    float s2 = fmaxf(z, w), s3 = fminf(z, w);
    float m0 = fmaxf(s0, s2), m2 = fminf(s0, s2);
    float m1 = fmaxf(s1, s3), m3 = fminf(s1, s3);
    x = m0;
    y = fmaxf(m1, m2);
    z = fminf(m1, m2);
    w = m3;
}

// Per-lane scan of one row's registers -> sorted top-4 + label logit (this lane's share).
__device__ __forceinline__ void scan_row(float4 (&v)[8], int label, int lane,
                                         float& t0, float& t1, float& t2, float& t3,
                                         float& lab) {
    t0 = t1 = t2 = t3 = -CUDART_INF_F;
    lab = -CUDART_INF_F;
    #pragma unroll
    for (int it = 0; it < 8; ++it) {
        const int i4 = it * 32 + lane;
        const int base = i4 * 4;
        if (it == 7 && i4 >= C_VEC4) {          // tail lanes: neutralize clamped dup
            v[it].x = v[it].y = v[it].z = v[it].w = -CUDART_INF_F;
        }
        const unsigned d = (unsigned)(label - base);
        if (d < 4u) {                            // rare: this quad holds the label
            if      (d == 0u) { lab = v[it].x; v[it].x = -CUDART_INF_F; }
            else if (d == 1u) { lab = v[it].y; v[it].y = -CUDART_INF_F; }
            else if (d == 2u) { lab = v[it].z; v[it].z = -CUDART_INF_F; }
            else              { lab = v[it].w; v[it].w = -CUDART_INF_F; }
        }
        sort4(v[it].x, v[it].y, v[it].z, v[it].w);
        merge4(t0, t1, t2, t3, v[it].x, v[it].y, v[it].z, v[it].w);
    }
}

__global__ __launch_bounds__(128)
void rowloss_kernel(const float* __restrict__ logits,
                    const int* __restrict__ labels32,
                    float* __restrict__ out) {
    const int gw   = (blockIdx.x * blockDim.x + threadIdx.x) >> 5;  // global warp
    const int wib  = (threadIdx.x >> 5);
    const int lane = threadIdx.x & 31;

    // Label dtype probe: int64-LE with labels<1000 => all odd 32-bit words zero.
    const bool is64 = ((labels32[1] | labels32[3] | labels32[5] | labels32[7]) == 0);
    const int rA = gw * 2, rB = rA + 1;
    const int labelA = is64 ? labels32[2 * rA] : labels32[rA];
    const int labelB = is64 ? labels32[2 * rB] : labels32[rB];

    const float4* __restrict__ rowA =
        reinterpret_cast<const float4*>(logits + (size_t)rA * C_COLS);
    const float4* __restrict__ rowB =
        reinterpret_cast<const float4*>(logits + (size_t)rB * C_COLS);

    // ---- Issue BOTH rows' loads up front: 16 LDG.128 in flight per thread.
    // Row B's memory latency is hidden under row A's ALU phase.
    float4 va[8], vb[8];
    #pragma unroll
    for (int it = 0; it < 8; ++it) {
        int i4 = it * 32 + lane;
        int i4c = i4 < C_VEC4 ? i4 : (C_VEC4 - 1);   // clamp (in-bounds), masked later
        va[it] = __ldcs(&rowA[i4c]);
        vb[it] = __ldcs(&rowB[i4c]);
    }

    float a0, a1, a2, a3, labA;
    float b0, b1, b2, b3, labB;
    scan_row(va, labelA, lane, a0, a1, a2, a3, labA);
    scan_row(vb, labelB, lane, b0, b1, b2, b3, labB);

    // ---- Interleaved butterfly merge for both rows (+ fused label broadcast):
    // 10 independent shuffles per round overlap the 26-cycle SHFL latency.
    #pragma unroll
    for (int off = 16; off; off >>= 1) {
        float sa0 = __shfl_xor_sync(0xffffffffu, a0, off);
        float sa1 = __shfl_xor_sync(0xffffffffu, a1, off);
        float sa2 = __shfl_xor_sync(0xffffffffu, a2, off);
        float sa3 = __shfl_xor_sync(0xffffffffu, a3, off);
        float sb0 = __shfl_xor_sync(0xffffffffu, b0, off);
        float sb1 = __shfl_xor_sync(0xffffffffu, b1, off);
        float sb2 = __shfl_xor_sync(0xffffffffu, b2, off);
        float sb3 = __shfl_xor_sync(0xffffffffu, b3, off);
        float sla = __shfl_xor_sync(0xffffffffu, labA, off);
        float slb = __shfl_xor_sync(0xffffffffu, labB, off);
        merge4(a0, a1, a2, a3, sa0, sa1, sa2, sa3);
        merge4(b0, b1, b2, b3, sb0, sb1, sb2, sb3);
        labA = fmaxf(labA, sla);
        labB = fmaxf(labB, slb);
    }

    // Per-warp loss pair -> per-block partial (deterministic order) -> one RED.
    __shared__ double sh_loss[WPB];
    if (lane == 0) {
        const float mA = fmaxf(labA, a0);
        const float sA = expf(labA - mA) + expf(a0 - mA) + expf(a1 - mA)
                       + expf(a2 - mA) + expf(a3 - mA);
        const float mB = fmaxf(labB, b0);
        const float sB = expf(labB - mB) + expf(b0 - mB) + expf(b1 - mB)
                       + expf(b2 - mB) + expf(b3 - mB);
        sh_loss[wib] = (double)(logf(sA) + mA - labA)
                     + (double)(logf(sB) + mB - labB);
    }
    __syncthreads();

    if (threadIdx.x == 0) {
        double acc = 0.0;
        #pragma unroll
        for (int i = 0; i < WPB; ++i) acc += sh_loss[i];
        atomicAdd(&g_acc, (unsigned long long)(acc * FIXSCALE));
        __threadfence();
        const unsigned ticket = atomicAdd(&g_count, 1u);
        if (ticket == (unsigned)(NBLK - 1)) {   // last block: finalize + reset
            __threadfence();
            const unsigned long long total = atomicAdd(&g_acc, 0ULL);
            out[0] = (float)((double)total * (1.0 / FIXSCALE) * (1.0 / (double)B_ROWS));
            g_acc   = 0ULL;                     // replay-safe reset
            __threadfence();
            g_count = 0u;
        }
    }
}

extern "C" void kernel_launch(void* const* d_in, const int* in_sizes, int n_in,
                              void* d_out, int out_size) {
    const float* logits   = (const float*)d_in[0];
    const int*   labels32 = (const int*)d_in[1];   // dtype probed in-kernel
    float* out = (float*)d_out;

    rowloss_kernel<<<NBLK, 128>>>(logits, labels32, out);
}